// round 5
// baseline (speedup 1.0000x reference)
#include <cuda_runtime.h>
#include <cuda_bf16.h>
#include <math.h>
#include <stdint.h>

// Problem constants
#define BB 8
#define LL 4096
#define DD 1024
#define HH 16
#define HD 64
#define TT 64
#define D2 2048

// ---------------- scratch (device globals; no allocation) ----------------
__device__ float g_q[TT * DD];
__device__ float g_kv[(size_t)BB * LL * D2];         // [B*L, 2048]: K | V
__device__ float g_attn[BB * TT * DD];
__device__ float g_tmp[BB * TT * DD];
__device__ float g_y[BB * TT * D2];
__device__ float g_h[(size_t)BB * LL * D2];

// ================= warp-MMA primitives (baseline PTX, compiles for sm_103) =================
__device__ __forceinline__ uint32_t smem_u32(const void* p) {
    uint32_t a;
    asm("{ .reg .u64 t; cvta.to.shared.u64 t, %1; cvt.u32.u64 %0, t; }" : "=r"(a) : "l"(p));
    return a;
}
__device__ __forceinline__ void ldm_x4(uint32_t* r, uint32_t addr) {
    asm volatile("ldmatrix.sync.aligned.m8n8.x4.shared.b16 {%0,%1,%2,%3}, [%4];"
        : "=r"(r[0]), "=r"(r[1]), "=r"(r[2]), "=r"(r[3]) : "r"(addr));
}
__device__ __forceinline__ void mma_bf16(float* d, const uint32_t* a, const uint32_t* b) {
    asm volatile("mma.sync.aligned.m16n8k16.row.col.f32.bf16.bf16.f32 "
        "{%0,%1,%2,%3}, {%4,%5,%6,%7}, {%8,%9}, {%0,%1,%2,%3};"
        : "+f"(d[0]), "+f"(d[1]), "+f"(d[2]), "+f"(d[3])
        : "r"(a[0]), "r"(a[1]), "r"(a[2]), "r"(a[3]), "r"(b[0]), "r"(b[1]));
}

// split one float4 into hi/lo bf16 pairs (each uint32 = 2 bf16)
__device__ __forceinline__ void split_cvt(float4 v, uint2& hi, uint2& lo) {
    uint32_t h01, h23, l01, l23;
    asm("cvt.rn.bf16x2.f32 %0, %1, %2;" : "=r"(h01) : "f"(v.y), "f"(v.x));
    asm("cvt.rn.bf16x2.f32 %0, %1, %2;" : "=r"(h23) : "f"(v.w), "f"(v.z));
    float hx = __uint_as_float(h01 << 16);
    float hy = __uint_as_float(h01 & 0xFFFF0000u);
    float hz = __uint_as_float(h23 << 16);
    float hw = __uint_as_float(h23 & 0xFFFF0000u);
    asm("cvt.rn.bf16x2.f32 %0, %1, %2;" : "=r"(l01) : "f"(v.y - hy), "f"(v.x - hx));
    asm("cvt.rn.bf16x2.f32 %0, %1, %2;" : "=r"(l23) : "f"(v.w - hw), "f"(v.z - hz));
    hi = make_uint2(h01, h23);
    lo = make_uint2(l01, l23);
}

// ============ warp-MMA GEMM: C[M,N] = A[M,K] @ W[N,K]^T + bias[N] ============
// fp32 in/out; 3-term bf16 split (hi*hi + lo*hi + hi*lo) -> rel err ~1.5e-5.
// 128x128 tile / CTA, 8 warps (2x4), warp tile 64x32, K-slab 32, double-buffered.
// N % 128 == 0, K % 32 == 0; M ragged (guarded).
// NOTE: W stored [N,K] (K contiguous) == col-major B for mma.row.col, so B
// fragments use NON-TRans ldmatrix with n-row addresses (same as A).
#define KSLAB 32
#define SROW  40                       // bf16 stride per row -> conflict-free ldmatrix
#define PLANE (128 * SROW * 2)         // 10240 bytes
#define BUFS  (4 * PLANE)              // Ahi, Alo, Bhi, Blo = 40960
#define GEMM_SMEM (2 * BUFS)           // 81920

__global__ __launch_bounds__(256, 1)
void gemm_mma_kernel(const float* __restrict__ A, const float* __restrict__ W,
                     const float* __restrict__ bias, float* __restrict__ C,
                     int M, int N, int K) {
    extern __shared__ char sm[];
    const uint32_t sb = smem_u32(sm);

    const int tid    = threadIdx.x;
    const int wid    = tid >> 5;
    const int lane   = tid & 31;
    const int warp_m = wid & 1;        // 0..1 -> 64-row halves
    const int warp_n = wid >> 1;       // 0..3 -> 32-col quarters
    const int row0   = blockIdx.y * 128;
    const int col0   = blockIdx.x * 128;

    // loader coords: idx = tid + i*256, r = idx>>3 (row), q = idx&7 (float4 in 32-col slab)
    const int lr = tid >> 3;           // +32 per i
    const int lq = tid & 7;

    float c[4][4][4];
    #pragma unroll
    for (int i = 0; i < 4; i++)
        #pragma unroll
        for (int j = 0; j < 4; j++)
            #pragma unroll
            for (int t = 0; t < 4; t++) c[i][j][t] = 0.f;

    const int nslab = K / KSLAB;
    float4 va[4], vw[4];

    // prologue: fetch slab 0
    #pragma unroll
    for (int i = 0; i < 4; i++) {
        int r = lr + 32 * i;
        va[i] = make_float4(0.f, 0.f, 0.f, 0.f);
        if (row0 + r < M) va[i] = *(const float4*)&A[(size_t)(row0 + r) * K + lq * 4];
        vw[i] = *(const float4*)&W[(size_t)(col0 + r) * K + lq * 4];
    }
    {   // store slab 0 into buffer 0
        char* base = sm;
        #pragma unroll
        for (int i = 0; i < 4; i++) {
            int r = lr + 32 * i;
            uint32_t off = (uint32_t)(r * (SROW * 2) + lq * 8);
            uint2 hi, lo;
            split_cvt(va[i], hi, lo);
            *(uint2*)(base + off)         = hi;
            *(uint2*)(base + PLANE + off) = lo;
            split_cvt(vw[i], hi, lo);
            *(uint2*)(base + 2 * PLANE + off) = hi;
            *(uint2*)(base + 3 * PLANE + off) = lo;
        }
    }
    __syncthreads();

    for (int s = 0; s < nslab; s++) {
        const int buf = s & 1;
        const uint32_t bbase = sb + buf * BUFS;

        // prefetch next slab to registers
        if (s + 1 < nslab) {
            const int k0 = (s + 1) * KSLAB;
            #pragma unroll
            for (int i = 0; i < 4; i++) {
                int r = lr + 32 * i;
                va[i] = make_float4(0.f, 0.f, 0.f, 0.f);
                if (row0 + r < M) va[i] = *(const float4*)&A[(size_t)(row0 + r) * K + k0 + lq * 4];
                vw[i] = *(const float4*)&W[(size_t)(col0 + r) * K + k0 + lq * 4];
            }
        }

        // compute this slab: 2 k-steps of 16
        #pragma unroll
        for (int ks = 0; ks < 2; ks++) {
            uint32_t ah[4][4], al[4][4], bh[2][4], bl[2][4];
            const int arow = warp_m * 64 + (lane & 15);
            const int akh  = lane >> 4;
            #pragma unroll
            for (int ma = 0; ma < 4; ma++) {
                uint32_t addr = bbase + (uint32_t)((arow + ma * 16) * (SROW * 2) + ks * 32 + akh * 16);
                ldm_x4(ah[ma], addr);
                ldm_x4(al[ma], addr + PLANE);
            }
            // B: non-trans ldmatrix; thread->address map builds {b0,b1} per 8-col atom:
            //   threads 0-7:  n 0-7,  k 0-7    (matrix0 = b0 of even atom)
            //   threads 8-15: n 0-7,  k 8-15   (matrix1 = b1 of even atom)
            //   threads16-23: n 8-15, k 0-7    (matrix2 = b0 of odd atom)
            //   threads24-31: n 8-15, k 8-15   (matrix3 = b1 of odd atom)
            const int bn  = warp_n * 32 + (lane & 7) + ((lane >> 4) << 3);
            const int bkh = (lane >> 3) & 1;
            #pragma unroll
            for (int p = 0; p < 2; p++) {
                uint32_t addr = bbase + 2 * PLANE
                              + (uint32_t)((bn + p * 16) * (SROW * 2) + ks * 32 + bkh * 16);
                ldm_x4(bh[p], addr);
                ldm_x4(bl[p], addr + PLANE);
            }
            #pragma unroll
            for (int ma = 0; ma < 4; ma++)
                #pragma unroll
                for (int na = 0; na < 4; na++) {
                    const uint32_t* bhp = &bh[na >> 1][(na & 1) * 2];
                    const uint32_t* blp = &bl[na >> 1][(na & 1) * 2];
                    mma_bf16(c[ma][na], ah[ma], bhp);   // hi*hi
                    mma_bf16(c[ma][na], al[ma], bhp);   // lo*hi
                    mma_bf16(c[ma][na], ah[ma], blp);   // hi*lo
                }
        }

        // store next slab into other buffer
        if (s + 1 < nslab) {
            char* base = sm + (buf ^ 1) * BUFS;
            #pragma unroll
            for (int i = 0; i < 4; i++) {
                int r = lr + 32 * i;
                uint32_t off = (uint32_t)(r * (SROW * 2) + lq * 8);
                uint2 hi, lo;
                split_cvt(va[i], hi, lo);
                *(uint2*)(base + off)         = hi;
                *(uint2*)(base + PLANE + off) = lo;
                split_cvt(vw[i], hi, lo);
                *(uint2*)(base + 2 * PLANE + off) = hi;
                *(uint2*)(base + 3 * PLANE + off) = lo;
            }
            __syncthreads();
        }
    }

    // epilogue: fragment -> gmem with bias
    const int g  = lane >> 2;          // 0..7
    const int tg = lane & 3;           // 0..3
    #pragma unroll
    for (int ma = 0; ma < 4; ma++) {
        #pragma unroll
        for (int half = 0; half < 2; half++) {
            int r = row0 + warp_m * 64 + ma * 16 + g + half * 8;
            if (r < M) {
                float* cp = C + (size_t)r * N;
                #pragma unroll
                for (int na = 0; na < 4; na++) {
                    int cc = col0 + warp_n * 32 + na * 8 + tg * 2;
                    float2 o;
                    o.x = c[ma][na][half * 2 + 0] + bias[cc + 0];
                    o.y = c[ma][na][half * 2 + 1] + bias[cc + 1];
                    *(float2*)(cp + cc) = o;
                }
            }
        }
    }
}

// ---------------- flash attention: one CTA per (b,h) ----------------
__global__ __launch_bounds__(256)
void flash_attn_kernel(const float* __restrict__ q, const float* __restrict__ kv,
                       float* __restrict__ attn_out) {
    const int bh = blockIdx.x;
    const int b = bh / HH, h = bh % HH;

    __shared__ float Qs[64][68];
    __shared__ float Ks[32][68];
    __shared__ float Vs[32][68];
    __shared__ float Ps[64][36];

    const int tid = threadIdx.x;
    const int tx = tid & 7;
    const int ty = tid >> 3;
    const int t0 = ty * 2, t1 = t0 + 1;

    {
        int r = tid >> 2;
        int cc = (tid & 3) * 16;
        const float* src = q + (size_t)r * DD + h * HD + cc;
        *(float4*)&Qs[r][cc]      = *(const float4*)(src);
        *(float4*)&Qs[r][cc + 4]  = *(const float4*)(src + 4);
        *(float4*)&Qs[r][cc + 8]  = *(const float4*)(src + 8);
        *(float4*)&Qs[r][cc + 12] = *(const float4*)(src + 12);
    }

    float m0 = -3.402823466e38f, m1 = -3.402823466e38f;
    float l0s = 0.f, l1s = 0.f;
    float o0[8], o1[8];
    #pragma unroll
    for (int j = 0; j < 8; j++) { o0[j] = 0.f; o1[j] = 0.f; }

    for (int lb = 0; lb < LL; lb += 32) {
        {
            int r = tid >> 3;
            int cc = (tid & 7) * 8;
            const float* kp = kv + (size_t)(b * LL + lb + r) * D2 + h * HD + cc;
            *(float4*)&Ks[r][cc]     = *(const float4*)kp;
            *(float4*)&Ks[r][cc + 4] = *(const float4*)(kp + 4);
            const float* vp = kp + DD;
            *(float4*)&Vs[r][cc]     = *(const float4*)vp;
            *(float4*)&Vs[r][cc + 4] = *(const float4*)(vp + 4);
        }
        __syncthreads();

        float s0[4] = {0.f, 0.f, 0.f, 0.f};
        float s1[4] = {0.f, 0.f, 0.f, 0.f};
        #pragma unroll 8
        for (int d = 0; d < 64; d++) {
            float a0 = Qs[t0][d];
            float a1 = Qs[t1][d];
            #pragma unroll
            for (int j = 0; j < 4; j++) {
                float kk = Ks[tx * 4 + j][d];
                s0[j] = fmaf(a0, kk, s0[j]);
                s1[j] = fmaf(a1, kk, s1[j]);
            }
        }
        #pragma unroll
        for (int j = 0; j < 4; j++) { s0[j] *= 0.125f; s1[j] *= 0.125f; }

        float rm0 = fmaxf(fmaxf(s0[0], s0[1]), fmaxf(s0[2], s0[3]));
        float rm1 = fmaxf(fmaxf(s1[0], s1[1]), fmaxf(s1[2], s1[3]));
        #pragma unroll
        for (int off = 1; off < 8; off <<= 1) {
            rm0 = fmaxf(rm0, __shfl_xor_sync(0xffffffffu, rm0, off));
            rm1 = fmaxf(rm1, __shfl_xor_sync(0xffffffffu, rm1, off));
        }
        float mn0 = fmaxf(m0, rm0), mn1 = fmaxf(m1, rm1);
        float c0 = __expf(m0 - mn0), c1 = __expf(m1 - mn1);

        float p0[4], p1[4];
        float rs0 = 0.f, rs1 = 0.f;
        #pragma unroll
        for (int j = 0; j < 4; j++) {
            p0[j] = __expf(s0[j] - mn0); rs0 += p0[j];
            p1[j] = __expf(s1[j] - mn1); rs1 += p1[j];
        }
        #pragma unroll
        for (int off = 1; off < 8; off <<= 1) {
            rs0 += __shfl_xor_sync(0xffffffffu, rs0, off);
            rs1 += __shfl_xor_sync(0xffffffffu, rs1, off);
        }
        l0s = l0s * c0 + rs0;
        l1s = l1s * c1 + rs1;
        m0 = mn0; m1 = mn1;
        #pragma unroll
        for (int j = 0; j < 8; j++) { o0[j] *= c0; o1[j] *= c1; }

        #pragma unroll
        for (int j = 0; j < 4; j++) {
            Ps[t0][tx * 4 + j] = p0[j];
            Ps[t1][tx * 4 + j] = p1[j];
        }
        __syncthreads();

        #pragma unroll 4
        for (int lc = 0; lc < 32; lc++) {
            float pv0 = Ps[t0][lc];
            float pv1 = Ps[t1][lc];
            #pragma unroll
            for (int j = 0; j < 8; j++) {
                float vv = Vs[lc][tx * 8 + j];
                o0[j] = fmaf(pv0, vv, o0[j]);
                o1[j] = fmaf(pv1, vv, o1[j]);
            }
        }
        __syncthreads();
    }

    float inv0 = 1.f / l0s, inv1 = 1.f / l1s;
    float* d0 = attn_out + (size_t)(b * TT + t0) * DD + h * HD + tx * 8;
    float* d1 = attn_out + (size_t)(b * TT + t1) * DD + h * HD + tx * 8;
    #pragma unroll
    for (int j = 0; j < 8; j++) { d0[j] = o0[j] * inv0; d1[j] = o1[j] * inv1; }
}

// ---------------- LayerNorm over last dim (1024), one CTA per row ----------------
__global__ __launch_bounds__(256)
void ln_kernel(const float* __restrict__ x, const float* __restrict__ gam,
               const float* __restrict__ bet, float* __restrict__ out) {
    const int row = blockIdx.x;
    const int tid = threadIdx.x;
    const float4* xr = (const float4*)(x + (size_t)row * DD);
    float4 v = xr[tid];
    float s  = v.x + v.y + v.z + v.w;
    float sq = v.x * v.x + v.y * v.y + v.z * v.z + v.w * v.w;
    #pragma unroll
    for (int off = 16; off > 0; off >>= 1) {
        s  += __shfl_xor_sync(0xffffffffu, s, off);
        sq += __shfl_xor_sync(0xffffffffu, sq, off);
    }
    __shared__ float ss[8], ssq[8];
    int w = tid >> 5, ln = tid & 31;
    if (ln == 0) { ss[w] = s; ssq[w] = sq; }
    __syncthreads();
    if (tid < 32) {
        float a = (tid < 8) ? ss[tid] : 0.f;
        float bq = (tid < 8) ? ssq[tid] : 0.f;
        #pragma unroll
        for (int off = 4; off > 0; off >>= 1) {
            a  += __shfl_xor_sync(0xffffffffu, a, off);
            bq += __shfl_xor_sync(0xffffffffu, bq, off);
        }
        if (tid == 0) { ss[0] = a; ssq[0] = bq; }
    }
    __syncthreads();
    float mu  = ss[0] * (1.f / 1024.f);
    float var = ssq[0] * (1.f / 1024.f) - mu * mu;
    float rstd = rsqrtf(var + 1e-5f);
    float4 gg = ((const float4*)gam)[tid];
    float4 bb = ((const float4*)bet)[tid];
    float4 o;
    o.x = (v.x - mu) * rstd * gg.x + bb.x;
    o.y = (v.y - mu) * rstd * gg.y + bb.y;
    o.z = (v.z - mu) * rstd * gg.z + bb.z;
    o.w = (v.w - mu) * rstd * gg.w + bb.w;
    ((float4*)(out + (size_t)row * DD))[tid] = o;
}

// ---------------- interp(y, T->L) + exact GELU -> h [B,L,2D] ----------------
__device__ __forceinline__ float gelu_exact(float x) {
    return 0.5f * x * (1.f + erff(x * 0.70710678118654752f));
}

__global__ __launch_bounds__(256)
void interp_gelu_kernel(const float* __restrict__ y, float* __restrict__ h) {
    const int bl = blockIdx.x;
    const int b = bl >> 12;
    const int l = bl & 4095;
    float pos = ((float)l + 0.5f) * (64.f / 4096.f) - 0.5f;
    pos = fminf(fmaxf(pos, 0.f), 63.f);
    int i0 = (int)floorf(pos);
    int i1 = min(i0 + 1, 63);
    float f = pos - (float)i0;

    const float4* y0 = (const float4*)(y + (size_t)(b * TT + i0) * D2);
    const float4* y1 = (const float4*)(y + (size_t)(b * TT + i1) * D2);
    float4* hp = (float4*)(h + (size_t)bl * D2);
    const int tid = threadIdx.x;
    #pragma unroll
    for (int i = 0; i < 2; i++) {
        int idx = tid + i * 256;
        float4 a = y0[idx];
        float4 cv = y1[idx];
        float4 r;
        r.x = gelu_exact(a.x + f * (cv.x - a.x));
        r.y = gelu_exact(a.y + f * (cv.y - a.y));
        r.z = gelu_exact(a.z + f * (cv.z - a.z));
        r.w = gelu_exact(a.w + f * (cv.w - a.w));
        hp[idx] = r;
    }
}

// ---------------- launch ----------------
extern "C" void kernel_launch(void* const* d_in, const int* in_sizes, int n_in,
                              void* d_out, int out_size) {
    const float* memory  = (const float*)d_in[0];   // [B,L,D]
    const float* query   = (const float*)d_in[1];   // [1,T,D]
    const float* in_w    = (const float*)d_in[2];   // [3D,D]
    const float* in_b    = (const float*)d_in[3];   // [3D]
    const float* out_w   = (const float*)d_in[4];   // [D,D]
    const float* out_b   = (const float*)d_in[5];   // [D]
    const float* lng     = (const float*)d_in[6];   // [D]
    const float* lnb     = (const float*)d_in[7];   // [D]
    const float* w1      = (const float*)d_in[8];   // [2D,D]
    const float* b1      = (const float*)d_in[9];   // [2D]
    const float* w2      = (const float*)d_in[10];  // [D,2D]
    const float* b2      = (const float*)d_in[11];  // [D]

    float* out = (float*)d_out;
    float* comp_out  = out;                          // [B,T,D]
    float* recon_out = out + (size_t)BB * TT * DD;   // [B,L,D]

    float *pq, *pkv, *pattn, *ptmp, *py, *ph;
    cudaGetSymbolAddress((void**)&pq,    g_q);
    cudaGetSymbolAddress((void**)&pkv,   g_kv);
    cudaGetSymbolAddress((void**)&pattn, g_attn);
    cudaGetSymbolAddress((void**)&ptmp,  g_tmp);
    cudaGetSymbolAddress((void**)&py,    g_y);
    cudaGetSymbolAddress((void**)&ph,    g_h);

    cudaFuncSetAttribute(gemm_mma_kernel,
                         cudaFuncAttributeMaxDynamicSharedMemorySize, GEMM_SMEM);

    // 1) q = query @ Wq^T + bq             [64, 1024], K=1024
    gemm_mma_kernel<<<dim3(8, 1), 256, GEMM_SMEM>>>(query, in_w, in_b, pq, TT, DD, DD);

    // 2) KV = memory @ [Wk;Wv]^T + [bk;bv] [32768, 2048], K=1024
    gemm_mma_kernel<<<dim3(16, 256), 256, GEMM_SMEM>>>(memory, in_w + DD * DD, in_b + DD,
                                                       pkv, BB * LL, D2, DD);

    // 3) flash attention -> g_attn [B,T,D]
    flash_attn_kernel<<<BB * HH, 256>>>(pq, pkv, pattn);

    // 4) out_proj: g_tmp = g_attn @ out_w^T + out_b  [512, 1024], K=1024
    gemm_mma_kernel<<<dim3(8, 4), 256, GEMM_SMEM>>>(pattn, out_w, out_b, ptmp,
                                                    BB * TT, DD, DD);

    // 5) LayerNorm -> compressed (directly into d_out)
    ln_kernel<<<BB * TT, 256>>>(ptmp, lng, lnb, comp_out);

    // 6) y = compressed @ w1^T + b1  [512, 2048], K=1024 (interp commutes with linear)
    gemm_mma_kernel<<<dim3(16, 4), 256, GEMM_SMEM>>>(comp_out, w1, b1, py, BB * TT, D2, DD);

    // 7) h = gelu(interp(y))   [B,L,2048]
    interp_gelu_kernel<<<BB * LL, 256>>>(py, ph);

    // 8) recon = h @ w2^T + b2  [32768, 1024], K=2048 -> d_out tail
    gemm_mma_kernel<<<dim3(8, 256), 256, GEMM_SMEM>>>(ph, w2, b2, recon_out,
                                                      BB * LL, DD, D2);
}